// round 16
// baseline (speedup 1.0000x reference)
#include <cuda_runtime.h>
#include <cuda_bf16.h>
#include <math.h>
#include <stdint.h>

typedef unsigned int uint;

#define B_  4
#define C_  512
#define T_  4096
#define C4_ 2048
#define KW  7

// ---------------- device scratch ----------------
__device__ float g_filt[12];
__device__ float g_h2[B_ * C_ * T_];                    // conv1 out (fp32)
__device__ __nv_bfloat16 g_xhi[B_ * C_ * T_];           // act1 out hi
__device__ __nv_bfloat16 g_xlo[B_ * C_ * T_];           // act1 out lo
__device__ __nv_bfloat16 g_yhi[B_ * C_ * T_];           // act2 out hi
__device__ __nv_bfloat16 g_ylo[B_ * C_ * T_];           // act2 out lo
__device__ __nv_bfloat16 g_w1hi[KW * C_ * C_];          // [k][o][ci]
__device__ __nv_bfloat16 g_w1lo[KW * C_ * C_];
__device__ __nv_bfloat16 g_w23hi[C_ * C_];              // [o][i]
__device__ __nv_bfloat16 g_w23lo[C_ * C_];
__device__ float g_w2[C4_ * C_];
__device__ float g_w3[C_ * C4_];
__device__ float g_Wpart[8 * C_ * C_];                  // partials stored [o][i]

// ---------------- mma.sync helper (baseline PTX, sm_80+) ----------------
#define MMA16816(d, a, b) \
    asm volatile("mma.sync.aligned.m16n8k16.row.col.f32.bf16.bf16.f32 " \
        "{%0,%1,%2,%3}, {%4,%5,%6,%7}, {%8,%9}, {%0,%1,%2,%3};" \
        : "+f"((d)[0]), "+f"((d)[1]), "+f"((d)[2]), "+f"((d)[3]) \
        : "r"((a)[0]), "r"((a)[1]), "r"((a)[2]), "r"((a)[3]), \
          "r"((b)[0]), "r"((b)[1]))

__device__ __forceinline__ void bsplit(float v, __nv_bfloat16& h, __nv_bfloat16& l) {
    h = __float2bfloat16(v);
    l = __float2bfloat16(v - __bfloat162float(h));
}

// ---------------- kaiser-sinc filter (mirrors numpy, double) ----------------
__device__ double bessel_i0(double x) {
    double sum = 1.0, term = 1.0, xx = x * x * 0.25;
    for (int k = 1; k < 64; k++) {
        term *= xx / ((double)k * (double)k);
        sum += term;
        if (term < sum * 1e-18) break;
    }
    return sum;
}

__global__ void k_filt() {
    if (threadIdx.x != 0) return;
    const double PI = 3.14159265358979323846;
    const double cutoff = 0.25, half_width = 0.3;
    const int half = 6;
    double delta_f = 4.0 * half_width;
    double A = 2.285 * (double)(half - 1) * PI * delta_f + 7.95;
    double beta;
    if (A > 50.0)       beta = 0.1102 * (A - 8.7);
    else if (A >= 21.0) beta = 0.5842 * pow(A - 21.0, 0.4) + 0.07886 * (A - 21.0);
    else                beta = 0.0;
    double i0b = bessel_i0(beta);
    double f[12]; double s = 0.0;
    for (int n = 0; n < 12; n++) {
        double r = 2.0 * (double)n / 11.0 - 1.0;
        double arg = 1.0 - r * r; if (arg < 0.0) arg = 0.0;
        double w = bessel_i0(beta * sqrt(arg)) / i0b;
        double t = (double)(n - 6) + 0.5;
        double xx = 2.0 * cutoff * t;
        double sc = sin(PI * xx) / (PI * xx);
        f[n] = 2.0 * cutoff * w * sc;
        s += f[n];
    }
    for (int n = 0; n < 12; n++) g_filt[n] = (float)(f[n] / s);
}

// ---------------- weight norm (fp32 out, for w2/w3) ----------------
__global__ void __launch_bounds__(256) k_wnorm(const float* __restrict__ v,
                                               const float* __restrict__ g,
                                               float* __restrict__ out, int len) {
    int co = blockIdx.x;
    const float* vr = v + (size_t)co * len;
    float s = 0.f;
    for (int i = threadIdx.x; i < len; i += 256) { float t = vr[i]; s += t * t; }
    __shared__ float red[256];
    red[threadIdx.x] = s;
    __syncthreads();
    for (int off = 128; off > 0; off >>= 1) {
        if (threadIdx.x < off) red[threadIdx.x] += red[threadIdx.x + off];
        __syncthreads();
    }
    float scale = g[co] / sqrtf(red[0]);
    float* orow = out + (size_t)co * len;
    for (int i = threadIdx.x; i < len; i += 256) orow[i] = vr[i] * scale;
}

// ---------------- weight norm for v1 -> bf16 split [k][o][ci] ----------------
__global__ void __launch_bounds__(256) k_wnorm1(const float* __restrict__ v,
                                                const float* __restrict__ g) {
    int co = blockIdx.x;
    const int len = C_ * KW;
    const float* vr = v + (size_t)co * len;
    float s = 0.f;
    for (int i = threadIdx.x; i < len; i += 256) { float t = vr[i]; s += t * t; }
    __shared__ float red[256];
    red[threadIdx.x] = s;
    __syncthreads();
    for (int off = 128; off > 0; off >>= 1) {
        if (threadIdx.x < off) red[threadIdx.x] += red[threadIdx.x + off];
        __syncthreads();
    }
    float scale = g[co] / sqrtf(red[0]);
    for (int i = threadIdx.x; i < len; i += 256) {
        int ci = i / 7, k = i - ci * 7;
        float w = vr[i] * scale;
        __nv_bfloat16 h, l; bsplit(w, h, l);
        size_t idx = ((size_t)k * 512 + co) * 512 + ci;
        g_w1hi[idx] = h; g_w1lo[idx] = l;
    }
}

// ---------------- Wt partials = (w3 @ w2)[o][i], split-K ----------------
__global__ void __launch_bounds__(256) k_gemmW() {
    __shared__ float sA[8][64];
    __shared__ float sB[8][68];
    int i0 = blockIdx.x * 64, o0 = blockIdx.y * 64, ms = blockIdx.z * 256;
    int tid = threadIdx.x, tx = tid & 15, ty = tid >> 4;
    float acc[4][4];
    #pragma unroll
    for (int a = 0; a < 4; a++)
        #pragma unroll
        for (int b = 0; b < 4; b++) acc[a][b] = 0.f;

    for (int mc = 0; mc < 256; mc += 8) {
        __syncthreads();
        #pragma unroll
        for (int it = 0; it < 2; it++) {
            int idx = tid + it * 256;
            int m = idx >> 6, i = idx & 63;
            sA[m][i] = g_w2[(size_t)(ms + mc + m) * 512 + i0 + i];
            int o = idx >> 3, m2 = idx & 7;
            sB[m2][o] = g_w3[(size_t)(o0 + o) * 2048 + ms + mc + m2];
        }
        __syncthreads();
        #pragma unroll
        for (int m = 0; m < 8; m++) {
            float av[4];
            #pragma unroll
            for (int q = 0; q < 4; q++) av[q] = sA[m][tx * 4 + q];
            #pragma unroll
            for (int oo = 0; oo < 4; oo++) {
                float w = sB[m][ty * 4 + oo];
                #pragma unroll
                for (int q = 0; q < 4; q++) acc[oo][q] += av[q] * w;
            }
        }
    }
    float* base = g_Wpart + (size_t)blockIdx.z * (512 * 512);
    #pragma unroll
    for (int oo = 0; oo < 4; oo++) {
        int o = o0 + ty * 4 + oo;
        #pragma unroll
        for (int q = 0; q < 4; q++) {
            int i = i0 + tx * 4 + q;
            base[(size_t)o * 512 + i] = acc[oo][q];   // [o][i]
        }
    }
}

__global__ void __launch_bounds__(256) k_redW() {
    int idx = blockIdx.x * 256 + threadIdx.x;       // idx = o*512 + i
    float s = 0.f;
    #pragma unroll
    for (int p = 0; p < 8; p++) s += g_Wpart[(size_t)p * (512 * 512) + idx];
    __nv_bfloat16 h, l; bsplit(s, h, l);
    g_w23hi[idx] = h; g_w23lo[idx] = l;
}

// ---------------- fused act1d emitting bf16 hi/lo ----------------
__global__ void __launch_bounds__(256) k_act_split(const float* __restrict__ in,
                                                   const float* __restrict__ la,
                                                   const float* __restrict__ lb,
                                                   __nv_bfloat16* __restrict__ ohi,
                                                   __nv_bfloat16* __restrict__ olo) {
    __shared__ float xs[T_];
    __shared__ float ss[2 * T_];
    int row = blockIdx.x;           // b*512 + c
    int c = row & (C_ - 1);
    const float* xr = in + (size_t)row * T_;
    for (int i = threadIdx.x; i < T_; i += 256) xs[i] = xr[i];
    __syncthreads();

    float a = expf(la[c]);
    float binv = 1.0f / (expf(lb[c]) + 1e-9f);
    float f[12];
    #pragma unroll
    for (int i = 0; i < 12; i++) f[i] = g_filt[i];

    for (int n = threadIdx.x; n < 2 * T_; n += 256) {
        int half = n >> 1;
        float u = 0.f;
        if ((n & 1) == 0) {
            #pragma unroll
            for (int m = 0; m < 6; m++) {
                int i = half - 3 + m;
                i = min(max(i, 0), T_ - 1);
                u += f[11 - 2 * m] * xs[i];
            }
        } else {
            #pragma unroll
            for (int m = 0; m < 6; m++) {
                int i = half - 2 + m;
                i = min(max(i, 0), T_ - 1);
                u += f[10 - 2 * m] * xs[i];
            }
        }
        u *= 2.0f;
        float sv = sinf(u * a);
        ss[n] = u + binv * sv * sv;
    }
    __syncthreads();

    for (int m = threadIdx.x; m < T_ / 2; m += 256) {
        float a0 = 0.f, a1 = 0.f;
        #pragma unroll
        for (int k = 0; k < 12; k++) {
            int j0 = 4 * m + k - 5; j0 = min(max(j0, 0), 2 * T_ - 1);
            int j1 = 4 * m + k - 3; j1 = min(max(j1, 0), 2 * T_ - 1);
            a0 += f[k] * ss[j0];
            a1 += f[k] * ss[j1];
        }
        __nv_bfloat16 h0, l0, h1, l1;
        bsplit(a0, h0, l0); bsplit(a1, h1, l1);
        __nv_bfloat162 hv; hv.x = h0; hv.y = h1;
        __nv_bfloat162 lv; lv.x = l0; lv.y = l1;
        *(__nv_bfloat162*)&ohi[(size_t)row * T_ + 2 * m] = hv;
        *(__nv_bfloat162*)&olo[(size_t)row * T_ + 2 * m] = lv;
    }
}

// ---------------- smem layout for mma conv kernels ----------------
// A: [128 o][64 ci] bf16, rows padded to 144B (conflict-free frag LDS)
// B: [t rows][64 ci] bf16 (transposed activations), rows padded to 136B
#define SA_STRIDE 144
#define SB_STRIDE 136
#define SM_AHI 0
#define SM_ALO 18432
#define SM_BHI 36864
#define SM_BLO 55296
#define SM_SZ  73728

// ---------------- conv1: K=7, 512->512, pad 3 via mma.sync bf16x3 ----------------
// grid (32, 4, 4); 256 thr; CTA tile 128o x 128t; warp 64o x 32t
__global__ void __launch_bounds__(256, 2) k_conv1_m() {
    extern __shared__ __align__(16) char smem[];
    char* sAhi = smem + SM_AHI; char* sAlo = smem + SM_ALO;
    char* sBhi = smem + SM_BHI; char* sBlo = smem + SM_BLO;
    const int tid = threadIdx.x;
    const int w = tid >> 5, lane = tid & 31;
    const int wo = w >> 2, wt = w & 3;           // warp: o-half, t-quarter
    const int g = lane >> 2, tg = lane & 3;
    const int b = blockIdx.z, o0 = blockIdx.y * 128, t0 = blockIdx.x * 128;

    const unsigned short* xhi = (const unsigned short*)g_xhi;
    const unsigned short* xlo = (const unsigned short*)g_xlo;
    const unsigned short* whi = (const unsigned short*)g_w1hi;
    const unsigned short* wlo = (const unsigned short*)g_w1lo;

    float d[4][4][4];
    #pragma unroll
    for (int i = 0; i < 4; i++)
        #pragma unroll
        for (int j = 0; j < 4; j++)
            #pragma unroll
            for (int r = 0; r < 4; r++) d[i][j][r] = 0.f;

    for (int cc = 0; cc < 512; cc += 64) {
        __syncthreads();
        // ---- fill B (transposed, halo +-3): rows t in [0,134), cols ci ----
        for (int u = tid; u < 64 * 134; u += 256) {
            int ci = u / 134, tp = u - ci * 134;
            int gt = t0 + tp - 3;
            size_t src = ((size_t)(b * 512 + cc + ci)) * T_ + gt;
            unsigned short vh = 0, vl = 0;
            if ((unsigned)gt < (unsigned)T_) { vh = xhi[src]; vl = xlo[src]; }
            *(unsigned short*)(sBhi + tp * SB_STRIDE + ci * 2) = vh;
            *(unsigned short*)(sBlo + tp * SB_STRIDE + ci * 2) = vl;
        }
        for (int k7 = 0; k7 < 7; k7++) {
            __syncthreads();
            // ---- fill A: [128 o][64 ci] ----
            #pragma unroll
            for (int it = 0; it < 4; it++) {
                int u = it * 256 + tid;              // 1024 uint4 per half
                int row = u >> 3, cv = u & 7;
                size_t src = ((size_t)(k7 * 512 + o0 + row)) * 512 + cc + cv * 8;
                *(uint4*)(sAhi + row * SA_STRIDE + cv * 16) = *(const uint4*)&whi[src];
                *(uint4*)(sAlo + row * SA_STRIDE + cv * 16) = *(const uint4*)&wlo[src];
            }
            __syncthreads();
            // ---- compute ----
            #pragma unroll
            for (int kc = 0; kc < 4; kc++) {
                const int coff = (kc * 16 + tg * 2) * 2;     // byte offset in ci
                uint bh[4][2], bl[4][2];
                #pragma unroll
                for (int nt = 0; nt < 4; nt++) {
                    int trow = wt * 32 + nt * 8 + g + k7;    // halo(3)+shift(k7-3)
                    const char* pb = sBhi + trow * SB_STRIDE + coff;
                    bh[nt][0] = *(const uint*)pb;
                    bh[nt][1] = *(const uint*)(pb + 16);
                    const char* pl = sBlo + trow * SB_STRIDE + coff;
                    bl[nt][0] = *(const uint*)pl;
                    bl[nt][1] = *(const uint*)(pl + 16);
                }
                uint ah[4][4];
                #pragma unroll
                for (int mt = 0; mt < 4; mt++) {
                    int orow = wo * 64 + mt * 16 + g;
                    const char* pa = sAhi + orow * SA_STRIDE + coff;
                    ah[mt][0] = *(const uint*)pa;
                    ah[mt][1] = *(const uint*)(pa + 8 * SA_STRIDE);
                    ah[mt][2] = *(const uint*)(pa + 16);
                    ah[mt][3] = *(const uint*)(pa + 8 * SA_STRIDE + 16);
                }
                #pragma unroll
                for (int mt = 0; mt < 4; mt++)
                    #pragma unroll
                    for (int nt = 0; nt < 4; nt++) MMA16816(d[mt][nt], ah[mt], bh[nt]);
                #pragma unroll
                for (int mt = 0; mt < 4; mt++)
                    #pragma unroll
                    for (int nt = 0; nt < 4; nt++) MMA16816(d[mt][nt], ah[mt], bl[nt]);
                uint al[4][4];
                #pragma unroll
                for (int mt = 0; mt < 4; mt++) {
                    int orow = wo * 64 + mt * 16 + g;
                    const char* pa = sAlo + orow * SA_STRIDE + coff;
                    al[mt][0] = *(const uint*)pa;
                    al[mt][1] = *(const uint*)(pa + 8 * SA_STRIDE);
                    al[mt][2] = *(const uint*)(pa + 16);
                    al[mt][3] = *(const uint*)(pa + 8 * SA_STRIDE + 16);
                }
                #pragma unroll
                for (int mt = 0; mt < 4; mt++)
                    #pragma unroll
                    for (int nt = 0; nt < 4; nt++) MMA16816(d[mt][nt], al[mt], bh[nt]);
            }
        }
    }
    // ---- store ----
    #pragma unroll
    for (int mt = 0; mt < 4; mt++) {
        int o = o0 + wo * 64 + mt * 16 + g;
        #pragma unroll
        for (int nt = 0; nt < 4; nt++) {
            int t = t0 + wt * 32 + nt * 8 + tg * 2;
            float2 v0; v0.x = d[mt][nt][0]; v0.y = d[mt][nt][1];
            float2 v1; v1.x = d[mt][nt][2]; v1.y = d[mt][nt][3];
            *(float2*)&g_h2[((size_t)(b * 512 + o)) * T_ + t] = v0;
            *(float2*)&g_h2[((size_t)(b * 512 + o + 8)) * T_ + t] = v1;
        }
    }
}

// ---------------- conv23: fused 1x1 (512x512) + residual via mma.sync ----------------
__global__ void __launch_bounds__(256, 2) k_conv23_m(const float* __restrict__ x,
                                                     float* __restrict__ out) {
    extern __shared__ __align__(16) char smem[];
    char* sAhi = smem + SM_AHI; char* sAlo = smem + SM_ALO;
    char* sBhi = smem + SM_BHI; char* sBlo = smem + SM_BLO;
    const int tid = threadIdx.x;
    const int w = tid >> 5, lane = tid & 31;
    const int wo = w >> 2, wt = w & 3;
    const int g = lane >> 2, tg = lane & 3;
    const int b = blockIdx.z, o0 = blockIdx.y * 128, t0 = blockIdx.x * 128;

    const unsigned short* yhi = (const unsigned short*)g_yhi;
    const unsigned short* ylo = (const unsigned short*)g_ylo;
    const unsigned short* whi = (const unsigned short*)g_w23hi;
    const unsigned short* wlo = (const unsigned short*)g_w23lo;

    float d[4][4][4];
    #pragma unroll
    for (int i = 0; i < 4; i++)
        #pragma unroll
        for (int j = 0; j < 4; j++)
            #pragma unroll
            for (int r = 0; r < 4; r++) d[i][j][r] = 0.f;

    for (int cc = 0; cc < 512; cc += 64) {
        __syncthreads();
        // ---- fill B (transposed): rows t in [0,128), cols ci ----
        for (int u = tid; u < 64 * 64; u += 256) {
            int ci = u >> 6, tp = (u & 63) * 2;
            size_t src = ((size_t)(b * 512 + cc + ci)) * T_ + t0 + tp;
            uint vh = *(const uint*)&yhi[src];
            uint vl = *(const uint*)&ylo[src];
            *(unsigned short*)(sBhi + tp * SB_STRIDE + ci * 2) = (unsigned short)vh;
            *(unsigned short*)(sBhi + (tp + 1) * SB_STRIDE + ci * 2) = (unsigned short)(vh >> 16);
            *(unsigned short*)(sBlo + tp * SB_STRIDE + ci * 2) = (unsigned short)vl;
            *(unsigned short*)(sBlo + (tp + 1) * SB_STRIDE + ci * 2) = (unsigned short)(vl >> 16);
        }
        // ---- fill A ----
        #pragma unroll
        for (int it = 0; it < 4; it++) {
            int u = it * 256 + tid;
            int row = u >> 3, cv = u & 7;
            size_t src = ((size_t)(o0 + row)) * 512 + cc + cv * 8;
            *(uint4*)(sAhi + row * SA_STRIDE + cv * 16) = *(const uint4*)&whi[src];
            *(uint4*)(sAlo + row * SA_STRIDE + cv * 16) = *(const uint4*)&wlo[src];
        }
        __syncthreads();
        #pragma unroll
        for (int kc = 0; kc < 4; kc++) {
            const int coff = (kc * 16 + tg * 2) * 2;
            uint bh[4][2], bl[4][2];
            #pragma unroll
            for (int nt = 0; nt < 4; nt++) {
                int trow = wt * 32 + nt * 8 + g;
                const char* pb = sBhi + trow * SB_STRIDE + coff;
                bh[nt][0] = *(const uint*)pb;
                bh[nt][1] = *(const uint*)(pb + 16);
                const char* pl = sBlo + trow * SB_STRIDE + coff;
                bl[nt][0] = *(const uint*)pl;
                bl[nt][1] = *(const uint*)(pl + 16);
            }
            uint ah[4][4];
            #pragma unroll
            for (int mt = 0; mt < 4; mt++) {
                int orow = wo * 64 + mt * 16 + g;
                const char* pa = sAhi + orow * SA_STRIDE + coff;
                ah[mt][0] = *(const uint*)pa;
                ah[mt][1] = *(const uint*)(pa + 8 * SA_STRIDE);
                ah[mt][2] = *(const uint*)(pa + 16);
                ah[mt][3] = *(const uint*)(pa + 8 * SA_STRIDE + 16);
            }
            #pragma unroll
            for (int mt = 0; mt < 4; mt++)
                #pragma unroll
                for (int nt = 0; nt < 4; nt++) MMA16816(d[mt][nt], ah[mt], bh[nt]);
            #pragma unroll
            for (int mt = 0; mt < 4; mt++)
                #pragma unroll
                for (int nt = 0; nt < 4; nt++) MMA16816(d[mt][nt], ah[mt], bl[nt]);
            uint al[4][4];
            #pragma unroll
            for (int mt = 0; mt < 4; mt++) {
                int orow = wo * 64 + mt * 16 + g;
                const char* pa = sAlo + orow * SA_STRIDE + coff;
                al[mt][0] = *(const uint*)pa;
                al[mt][1] = *(const uint*)(pa + 8 * SA_STRIDE);
                al[mt][2] = *(const uint*)(pa + 16);
                al[mt][3] = *(const uint*)(pa + 8 * SA_STRIDE + 16);
            }
            #pragma unroll
            for (int mt = 0; mt < 4; mt++)
                #pragma unroll
                for (int nt = 0; nt < 4; nt++) MMA16816(d[mt][nt], al[mt], bh[nt]);
        }
    }
    // ---- store + residual ----
    #pragma unroll
    for (int mt = 0; mt < 4; mt++) {
        int o = o0 + wo * 64 + mt * 16 + g;
        #pragma unroll
        for (int nt = 0; nt < 4; nt++) {
            int t = t0 + wt * 32 + nt * 8 + tg * 2;
            size_t i0 = ((size_t)(b * 512 + o)) * T_ + t;
            size_t i1 = ((size_t)(b * 512 + o + 8)) * T_ + t;
            float2 x0 = *(const float2*)&x[i0];
            float2 x1 = *(const float2*)&x[i1];
            float2 v0; v0.x = d[mt][nt][0] + x0.x; v0.y = d[mt][nt][1] + x0.y;
            float2 v1; v1.x = d[mt][nt][2] + x1.x; v1.y = d[mt][nt][3] + x1.y;
            *(float2*)&out[i0] = v0;
            *(float2*)&out[i1] = v1;
        }
    }
}

// ---------------- launch ----------------
extern "C" void kernel_launch(void* const* d_in, const int* in_sizes, int n_in,
                              void* d_out, int out_size) {
    (void)in_sizes; (void)n_in; (void)out_size;
    const float* x  = (const float*)d_in[0];
    const float* a1 = (const float*)d_in[1];
    const float* b1 = (const float*)d_in[2];
    const float* v1 = (const float*)d_in[3];
    const float* g1 = (const float*)d_in[4];
    const float* a2 = (const float*)d_in[5];
    const float* b2 = (const float*)d_in[6];
    const float* v2 = (const float*)d_in[7];
    const float* g2 = (const float*)d_in[8];
    const float* v3 = (const float*)d_in[9];
    const float* g3 = (const float*)d_in[10];
    float* out = (float*)d_out;

    float *w2p = nullptr, *w3p = nullptr, *h2p = nullptr;
    __nv_bfloat16 *xhip = nullptr, *xlop = nullptr, *yhip = nullptr, *ylop = nullptr;
    cudaGetSymbolAddress((void**)&w2p, g_w2);
    cudaGetSymbolAddress((void**)&w3p, g_w3);
    cudaGetSymbolAddress((void**)&h2p, g_h2);
    cudaGetSymbolAddress((void**)&xhip, g_xhi);
    cudaGetSymbolAddress((void**)&xlop, g_xlo);
    cudaGetSymbolAddress((void**)&yhip, g_yhi);
    cudaGetSymbolAddress((void**)&ylop, g_ylo);

    cudaFuncSetAttribute(k_conv1_m, cudaFuncAttributeMaxDynamicSharedMemorySize, SM_SZ);
    cudaFuncSetAttribute(k_conv23_m, cudaFuncAttributeMaxDynamicSharedMemorySize, SM_SZ);

    k_filt<<<1, 32>>>();                                          // 1
    k_wnorm1<<<C_, 256>>>(v1, g1);                                // 2
    k_wnorm<<<C4_, 256>>>(v2, g2, w2p, C_);                       // 3
    k_wnorm<<<C_,  256>>>(v3, g3, w3p, C4_);                      // 4
    k_act_split<<<B_ * C_, 256>>>(x, a1, b1, xhip, xlop);         // 5
    k_conv1_m<<<dim3(32, 4, 4), 256, SM_SZ>>>();                  // 6 (profiled)
    k_gemmW<<<dim3(8, 8, 8), 256>>>();                            // 7
    k_redW<<<1024, 256>>>();                                      // 8
    k_act_split<<<B_ * C_, 256>>>(h2p, a2, b2, yhip, ylop);       // 9
    k_conv23_m<<<dim3(32, 4, 4), 256, SM_SZ>>>(x, out);           // 10
}

// round 17
// speedup vs baseline: 1.0018x; 1.0018x over previous
#include <cuda_runtime.h>
#include <cuda_bf16.h>
#include <math.h>
#include <stdint.h>

typedef unsigned int uint;

#define B_  4
#define C_  512
#define T_  4096
#define C4_ 2048
#define KW  7

// ---------------- device scratch ----------------
__device__ float g_filt[12];
__device__ float g_h2[B_ * C_ * T_];                    // conv1 out (fp32)
__device__ __nv_bfloat16 g_xhi[B_ * C_ * T_];           // act1 out hi
__device__ __nv_bfloat16 g_xlo[B_ * C_ * T_];           // act1 out lo
__device__ __nv_bfloat16 g_yhi[B_ * C_ * T_];           // act2 out hi
__device__ __nv_bfloat16 g_ylo[B_ * C_ * T_];           // act2 out lo
__device__ __nv_bfloat16 g_w1hi[KW * C_ * C_];          // [k][o][ci]
__device__ __nv_bfloat16 g_w1lo[KW * C_ * C_];
__device__ __nv_bfloat16 g_w23hi[C_ * C_];              // [o][i]
__device__ __nv_bfloat16 g_w23lo[C_ * C_];
__device__ float g_w2[C4_ * C_];
__device__ float g_w3[C_ * C4_];
__device__ float g_Wpart[8 * C_ * C_];                  // partials stored [o][i]

// ---------------- mma.sync helper (baseline PTX, sm_80+) ----------------
#define MMA16816(d, a, b) \
    asm volatile("mma.sync.aligned.m16n8k16.row.col.f32.bf16.bf16.f32 " \
        "{%0,%1,%2,%3}, {%4,%5,%6,%7}, {%8,%9}, {%0,%1,%2,%3};" \
        : "+f"((d)[0]), "+f"((d)[1]), "+f"((d)[2]), "+f"((d)[3]) \
        : "r"((a)[0]), "r"((a)[1]), "r"((a)[2]), "r"((a)[3]), \
          "r"((b)[0]), "r"((b)[1]))

__device__ __forceinline__ void bsplit(float v, __nv_bfloat16& h, __nv_bfloat16& l) {
    h = __float2bfloat16(v);
    l = __float2bfloat16(v - __bfloat162float(h));
}

// ---------------- kaiser-sinc filter (mirrors numpy, double) ----------------
__device__ double bessel_i0(double x) {
    double sum = 1.0, term = 1.0, xx = x * x * 0.25;
    for (int k = 1; k < 64; k++) {
        term *= xx / ((double)k * (double)k);
        sum += term;
        if (term < sum * 1e-18) break;
    }
    return sum;
}

__global__ void k_filt() {
    if (threadIdx.x != 0) return;
    const double PI = 3.14159265358979323846;
    const double cutoff = 0.25, half_width = 0.3;
    const int half = 6;
    double delta_f = 4.0 * half_width;
    double A = 2.285 * (double)(half - 1) * PI * delta_f + 7.95;
    double beta;
    if (A > 50.0)       beta = 0.1102 * (A - 8.7);
    else if (A >= 21.0) beta = 0.5842 * pow(A - 21.0, 0.4) + 0.07886 * (A - 21.0);
    else                beta = 0.0;
    double i0b = bessel_i0(beta);
    double f[12]; double s = 0.0;
    for (int n = 0; n < 12; n++) {
        double r = 2.0 * (double)n / 11.0 - 1.0;
        double arg = 1.0 - r * r; if (arg < 0.0) arg = 0.0;
        double w = bessel_i0(beta * sqrt(arg)) / i0b;
        double t = (double)(n - 6) + 0.5;
        double xx = 2.0 * cutoff * t;
        double sc = sin(PI * xx) / (PI * xx);
        f[n] = 2.0 * cutoff * w * sc;
        s += f[n];
    }
    for (int n = 0; n < 12; n++) g_filt[n] = (float)(f[n] / s);
}

// ---------------- weight norm (fp32 out, for w2/w3) ----------------
__global__ void __launch_bounds__(256) k_wnorm(const float* __restrict__ v,
                                               const float* __restrict__ g,
                                               float* __restrict__ out, int len) {
    int co = blockIdx.x;
    const float* vr = v + (size_t)co * len;
    float s = 0.f;
    for (int i = threadIdx.x; i < len; i += 256) { float t = vr[i]; s += t * t; }
    __shared__ float red[256];
    red[threadIdx.x] = s;
    __syncthreads();
    for (int off = 128; off > 0; off >>= 1) {
        if (threadIdx.x < off) red[threadIdx.x] += red[threadIdx.x + off];
        __syncthreads();
    }
    float scale = g[co] / sqrtf(red[0]);
    float* orow = out + (size_t)co * len;
    for (int i = threadIdx.x; i < len; i += 256) orow[i] = vr[i] * scale;
}

// ---------------- weight norm for v1 -> bf16 split [k][o][ci] ----------------
__global__ void __launch_bounds__(256) k_wnorm1(const float* __restrict__ v,
                                                const float* __restrict__ g) {
    int co = blockIdx.x;
    const int len = C_ * KW;
    const float* vr = v + (size_t)co * len;
    float s = 0.f;
    for (int i = threadIdx.x; i < len; i += 256) { float t = vr[i]; s += t * t; }
    __shared__ float red[256];
    red[threadIdx.x] = s;
    __syncthreads();
    for (int off = 128; off > 0; off >>= 1) {
        if (threadIdx.x < off) red[threadIdx.x] += red[threadIdx.x + off];
        __syncthreads();
    }
    float scale = g[co] / sqrtf(red[0]);
    for (int i = threadIdx.x; i < len; i += 256) {
        int ci = i / 7, k = i - ci * 7;
        float w = vr[i] * scale;
        __nv_bfloat16 h, l; bsplit(w, h, l);
        size_t idx = ((size_t)k * 512 + co) * 512 + ci;
        g_w1hi[idx] = h; g_w1lo[idx] = l;
    }
}

// ---------------- Wt partials = (w3 @ w2)[o][i], split-K ----------------
__global__ void __launch_bounds__(256) k_gemmW() {
    __shared__ float sA[8][64];
    __shared__ float sB[8][68];
    int i0 = blockIdx.x * 64, o0 = blockIdx.y * 64, ms = blockIdx.z * 256;
    int tid = threadIdx.x, tx = tid & 15, ty = tid >> 4;
    float acc[4][4];
    #pragma unroll
    for (int a = 0; a < 4; a++)
        #pragma unroll
        for (int b = 0; b < 4; b++) acc[a][b] = 0.f;

    for (int mc = 0; mc < 256; mc += 8) {
        __syncthreads();
        #pragma unroll
        for (int it = 0; it < 2; it++) {
            int idx = tid + it * 256;
            int m = idx >> 6, i = idx & 63;
            sA[m][i] = g_w2[(size_t)(ms + mc + m) * 512 + i0 + i];
            int o = idx >> 3, m2 = idx & 7;
            sB[m2][o] = g_w3[(size_t)(o0 + o) * 2048 + ms + mc + m2];
        }
        __syncthreads();
        #pragma unroll
        for (int m = 0; m < 8; m++) {
            float av[4];
            #pragma unroll
            for (int q = 0; q < 4; q++) av[q] = sA[m][tx * 4 + q];
            #pragma unroll
            for (int oo = 0; oo < 4; oo++) {
                float w = sB[m][ty * 4 + oo];
                #pragma unroll
                for (int q = 0; q < 4; q++) acc[oo][q] += av[q] * w;
            }
        }
    }
    float* base = g_Wpart + (size_t)blockIdx.z * (512 * 512);
    #pragma unroll
    for (int oo = 0; oo < 4; oo++) {
        int o = o0 + ty * 4 + oo;
        #pragma unroll
        for (int q = 0; q < 4; q++) {
            int i = i0 + tx * 4 + q;
            base[(size_t)o * 512 + i] = acc[oo][q];   // [o][i]
        }
    }
}

__global__ void __launch_bounds__(256) k_redW() {
    int idx = blockIdx.x * 256 + threadIdx.x;       // idx = o*512 + i
    float s = 0.f;
    #pragma unroll
    for (int p = 0; p < 8; p++) s += g_Wpart[(size_t)p * (512 * 512) + idx];
    __nv_bfloat16 h, l; bsplit(s, h, l);
    g_w23hi[idx] = h; g_w23lo[idx] = l;
}

// ---------------- fused act1d emitting bf16 hi/lo ----------------
__global__ void __launch_bounds__(256) k_act_split(const float* __restrict__ in,
                                                   const float* __restrict__ la,
                                                   const float* __restrict__ lb,
                                                   __nv_bfloat16* __restrict__ ohi,
                                                   __nv_bfloat16* __restrict__ olo) {
    __shared__ float xs[T_];
    __shared__ float ss[2 * T_];
    int row = blockIdx.x;           // b*512 + c
    int c = row & (C_ - 1);
    const float* xr = in + (size_t)row * T_;
    for (int i = threadIdx.x; i < T_; i += 256) xs[i] = xr[i];
    __syncthreads();

    float a = expf(la[c]);
    float binv = 1.0f / (expf(lb[c]) + 1e-9f);
    float f[12];
    #pragma unroll
    for (int i = 0; i < 12; i++) f[i] = g_filt[i];

    for (int n = threadIdx.x; n < 2 * T_; n += 256) {
        int half = n >> 1;
        float u = 0.f;
        if ((n & 1) == 0) {
            #pragma unroll
            for (int m = 0; m < 6; m++) {
                int i = half - 3 + m;
                i = min(max(i, 0), T_ - 1);
                u += f[11 - 2 * m] * xs[i];
            }
        } else {
            #pragma unroll
            for (int m = 0; m < 6; m++) {
                int i = half - 2 + m;
                i = min(max(i, 0), T_ - 1);
                u += f[10 - 2 * m] * xs[i];
            }
        }
        u *= 2.0f;
        float sv = sinf(u * a);
        ss[n] = u + binv * sv * sv;
    }
    __syncthreads();

    for (int m = threadIdx.x; m < T_ / 2; m += 256) {
        float a0 = 0.f, a1 = 0.f;
        #pragma unroll
        for (int k = 0; k < 12; k++) {
            int j0 = 4 * m + k - 5; j0 = min(max(j0, 0), 2 * T_ - 1);
            int j1 = 4 * m + k - 3; j1 = min(max(j1, 0), 2 * T_ - 1);
            a0 += f[k] * ss[j0];
            a1 += f[k] * ss[j1];
        }
        __nv_bfloat16 h0, l0, h1, l1;
        bsplit(a0, h0, l0); bsplit(a1, h1, l1);
        __nv_bfloat162 hv; hv.x = h0; hv.y = h1;
        __nv_bfloat162 lv; lv.x = l0; lv.y = l1;
        *(__nv_bfloat162*)&ohi[(size_t)row * T_ + 2 * m] = hv;
        *(__nv_bfloat162*)&olo[(size_t)row * T_ + 2 * m] = lv;
    }
}

// ---------------- smem layout for mma conv kernels ----------------
// A: [128 o][64 ci] bf16, rows padded to 144B (conflict-free frag LDS)
// B: [t rows][64 ci] bf16 (transposed activations), rows padded to 136B
#define SA_STRIDE 144
#define SB_STRIDE 136
#define SM_AHI 0
#define SM_ALO 18432
#define SM_BHI 36864
#define SM_BLO 55296
#define SM_SZ  73728

// ---------------- conv1: K=7, 512->512, pad 3 via mma.sync bf16x3 ----------------
// grid (32, 4, 4); 256 thr; CTA tile 128o x 128t; warp 64o x 32t
__global__ void __launch_bounds__(256, 2) k_conv1_m() {
    extern __shared__ __align__(16) char smem[];
    char* sAhi = smem + SM_AHI; char* sAlo = smem + SM_ALO;
    char* sBhi = smem + SM_BHI; char* sBlo = smem + SM_BLO;
    const int tid = threadIdx.x;
    const int w = tid >> 5, lane = tid & 31;
    const int wo = w >> 2, wt = w & 3;           // warp: o-half, t-quarter
    const int g = lane >> 2, tg = lane & 3;
    const int b = blockIdx.z, o0 = blockIdx.y * 128, t0 = blockIdx.x * 128;

    const unsigned short* xhi = (const unsigned short*)g_xhi;
    const unsigned short* xlo = (const unsigned short*)g_xlo;
    const unsigned short* whi = (const unsigned short*)g_w1hi;
    const unsigned short* wlo = (const unsigned short*)g_w1lo;

    float d[4][4][4];
    #pragma unroll
    for (int i = 0; i < 4; i++)
        #pragma unroll
        for (int j = 0; j < 4; j++)
            #pragma unroll
            for (int r = 0; r < 4; r++) d[i][j][r] = 0.f;

    for (int cc = 0; cc < 512; cc += 64) {
        __syncthreads();
        // ---- fill B (transposed, halo +-3): rows t in [0,134), cols ci ----
        for (int u = tid; u < 64 * 134; u += 256) {
            int ci = u / 134, tp = u - ci * 134;
            int gt = t0 + tp - 3;
            size_t src = ((size_t)(b * 512 + cc + ci)) * T_ + gt;
            unsigned short vh = 0, vl = 0;
            if ((unsigned)gt < (unsigned)T_) { vh = xhi[src]; vl = xlo[src]; }
            *(unsigned short*)(sBhi + tp * SB_STRIDE + ci * 2) = vh;
            *(unsigned short*)(sBlo + tp * SB_STRIDE + ci * 2) = vl;
        }
        for (int k7 = 0; k7 < 7; k7++) {
            __syncthreads();
            // ---- fill A: [128 o][64 ci] ----
            #pragma unroll
            for (int it = 0; it < 4; it++) {
                int u = it * 256 + tid;              // 1024 uint4 per half
                int row = u >> 3, cv = u & 7;
                size_t src = ((size_t)(k7 * 512 + o0 + row)) * 512 + cc + cv * 8;
                *(uint4*)(sAhi + row * SA_STRIDE + cv * 16) = *(const uint4*)&whi[src];
                *(uint4*)(sAlo + row * SA_STRIDE + cv * 16) = *(const uint4*)&wlo[src];
            }
            __syncthreads();
            // ---- compute ----
            #pragma unroll
            for (int kc = 0; kc < 4; kc++) {
                const int coff = (kc * 16 + tg * 2) * 2;     // byte offset in ci
                uint bh[4][2], bl[4][2];
                #pragma unroll
                for (int nt = 0; nt < 4; nt++) {
                    int trow = wt * 32 + nt * 8 + g + k7;    // halo(3)+shift(k7-3)
                    const char* pb = sBhi + trow * SB_STRIDE + coff;
                    bh[nt][0] = *(const uint*)pb;
                    bh[nt][1] = *(const uint*)(pb + 16);
                    const char* pl = sBlo + trow * SB_STRIDE + coff;
                    bl[nt][0] = *(const uint*)pl;
                    bl[nt][1] = *(const uint*)(pl + 16);
                }
                uint ah[4][4];
                #pragma unroll
                for (int mt = 0; mt < 4; mt++) {
                    int orow = wo * 64 + mt * 16 + g;
                    const char* pa = sAhi + orow * SA_STRIDE + coff;
                    ah[mt][0] = *(const uint*)pa;
                    ah[mt][1] = *(const uint*)(pa + 8 * SA_STRIDE);
                    ah[mt][2] = *(const uint*)(pa + 16);
                    ah[mt][3] = *(const uint*)(pa + 8 * SA_STRIDE + 16);
                }
                #pragma unroll
                for (int mt = 0; mt < 4; mt++)
                    #pragma unroll
                    for (int nt = 0; nt < 4; nt++) MMA16816(d[mt][nt], ah[mt], bh[nt]);
                #pragma unroll
                for (int mt = 0; mt < 4; mt++)
                    #pragma unroll
                    for (int nt = 0; nt < 4; nt++) MMA16816(d[mt][nt], ah[mt], bl[nt]);
                uint al[4][4];
                #pragma unroll
                for (int mt = 0; mt < 4; mt++) {
                    int orow = wo * 64 + mt * 16 + g;
                    const char* pa = sAlo + orow * SA_STRIDE + coff;
                    al[mt][0] = *(const uint*)pa;
                    al[mt][1] = *(const uint*)(pa + 8 * SA_STRIDE);
                    al[mt][2] = *(const uint*)(pa + 16);
                    al[mt][3] = *(const uint*)(pa + 8 * SA_STRIDE + 16);
                }
                #pragma unroll
                for (int mt = 0; mt < 4; mt++)
                    #pragma unroll
                    for (int nt = 0; nt < 4; nt++) MMA16816(d[mt][nt], al[mt], bh[nt]);
            }
        }
    }
    // ---- store ----
    #pragma unroll
    for (int mt = 0; mt < 4; mt++) {
        int o = o0 + wo * 64 + mt * 16 + g;
        #pragma unroll
        for (int nt = 0; nt < 4; nt++) {
            int t = t0 + wt * 32 + nt * 8 + tg * 2;
            float2 v0; v0.x = d[mt][nt][0]; v0.y = d[mt][nt][1];
            float2 v1; v1.x = d[mt][nt][2]; v1.y = d[mt][nt][3];
            *(float2*)&g_h2[((size_t)(b * 512 + o)) * T_ + t] = v0;
            *(float2*)&g_h2[((size_t)(b * 512 + o + 8)) * T_ + t] = v1;
        }
    }
}

// ---------------- conv23: fused 1x1 (512x512) + residual via mma.sync ----------------
__global__ void __launch_bounds__(256, 2) k_conv23_m(const float* __restrict__ x,
                                                     float* __restrict__ out) {
    extern __shared__ __align__(16) char smem[];
    char* sAhi = smem + SM_AHI; char* sAlo = smem + SM_ALO;
    char* sBhi = smem + SM_BHI; char* sBlo = smem + SM_BLO;
    const int tid = threadIdx.x;
    const int w = tid >> 5, lane = tid & 31;
    const int wo = w >> 2, wt = w & 3;
    const int g = lane >> 2, tg = lane & 3;
    const int b = blockIdx.z, o0 = blockIdx.y * 128, t0 = blockIdx.x * 128;

    const unsigned short* yhi = (const unsigned short*)g_yhi;
    const unsigned short* ylo = (const unsigned short*)g_ylo;
    const unsigned short* whi = (const unsigned short*)g_w23hi;
    const unsigned short* wlo = (const unsigned short*)g_w23lo;

    float d[4][4][4];
    #pragma unroll
    for (int i = 0; i < 4; i++)
        #pragma unroll
        for (int j = 0; j < 4; j++)
            #pragma unroll
            for (int r = 0; r < 4; r++) d[i][j][r] = 0.f;

    for (int cc = 0; cc < 512; cc += 64) {
        __syncthreads();
        // ---- fill B (transposed): rows t in [0,128), cols ci ----
        for (int u = tid; u < 64 * 64; u += 256) {
            int ci = u >> 6, tp = (u & 63) * 2;
            size_t src = ((size_t)(b * 512 + cc + ci)) * T_ + t0 + tp;
            uint vh = *(const uint*)&yhi[src];
            uint vl = *(const uint*)&ylo[src];
            *(unsigned short*)(sBhi + tp * SB_STRIDE + ci * 2) = (unsigned short)vh;
            *(unsigned short*)(sBhi + (tp + 1) * SB_STRIDE + ci * 2) = (unsigned short)(vh >> 16);
            *(unsigned short*)(sBlo + tp * SB_STRIDE + ci * 2) = (unsigned short)vl;
            *(unsigned short*)(sBlo + (tp + 1) * SB_STRIDE + ci * 2) = (unsigned short)(vl >> 16);
        }
        // ---- fill A ----
        #pragma unroll
        for (int it = 0; it < 4; it++) {
            int u = it * 256 + tid;
            int row = u >> 3, cv = u & 7;
            size_t src = ((size_t)(o0 + row)) * 512 + cc + cv * 8;
            *(uint4*)(sAhi + row * SA_STRIDE + cv * 16) = *(const uint4*)&whi[src];
            *(uint4*)(sAlo + row * SA_STRIDE + cv * 16) = *(const uint4*)&wlo[src];
        }
        __syncthreads();
        #pragma unroll
        for (int kc = 0; kc < 4; kc++) {
            const int coff = (kc * 16 + tg * 2) * 2;
            uint bh[4][2], bl[4][2];
            #pragma unroll
            for (int nt = 0; nt < 4; nt++) {
                int trow = wt * 32 + nt * 8 + g;
                const char* pb = sBhi + trow * SB_STRIDE + coff;
                bh[nt][0] = *(const uint*)pb;
                bh[nt][1] = *(const uint*)(pb + 16);
                const char* pl = sBlo + trow * SB_STRIDE + coff;
                bl[nt][0] = *(const uint*)pl;
                bl[nt][1] = *(const uint*)(pl + 16);
            }
            uint ah[4][4];
            #pragma unroll
            for (int mt = 0; mt < 4; mt++) {
                int orow = wo * 64 + mt * 16 + g;
                const char* pa = sAhi + orow * SA_STRIDE + coff;
                ah[mt][0] = *(const uint*)pa;
                ah[mt][1] = *(const uint*)(pa + 8 * SA_STRIDE);
                ah[mt][2] = *(const uint*)(pa + 16);
                ah[mt][3] = *(const uint*)(pa + 8 * SA_STRIDE + 16);
            }
            #pragma unroll
            for (int mt = 0; mt < 4; mt++)
                #pragma unroll
                for (int nt = 0; nt < 4; nt++) MMA16816(d[mt][nt], ah[mt], bh[nt]);
            #pragma unroll
            for (int mt = 0; mt < 4; mt++)
                #pragma unroll
                for (int nt = 0; nt < 4; nt++) MMA16816(d[mt][nt], ah[mt], bl[nt]);
            uint al[4][4];
            #pragma unroll
            for (int mt = 0; mt < 4; mt++) {
                int orow = wo * 64 + mt * 16 + g;
                const char* pa = sAlo + orow * SA_STRIDE + coff;
                al[mt][0] = *(const uint*)pa;
                al[mt][1] = *(const uint*)(pa + 8 * SA_STRIDE);
                al[mt][2] = *(const uint*)(pa + 16);
                al[mt][3] = *(const uint*)(pa + 8 * SA_STRIDE + 16);
            }
            #pragma unroll
            for (int mt = 0; mt < 4; mt++)
                #pragma unroll
                for (int nt = 0; nt < 4; nt++) MMA16816(d[mt][nt], al[mt], bh[nt]);
        }
    }
    // ---- store + residual ----
    #pragma unroll
    for (int mt = 0; mt < 4; mt++) {
        int o = o0 + wo * 64 + mt * 16 + g;
        #pragma unroll
        for (int nt = 0; nt < 4; nt++) {
            int t = t0 + wt * 32 + nt * 8 + tg * 2;
            size_t i0 = ((size_t)(b * 512 + o)) * T_ + t;
            size_t i1 = ((size_t)(b * 512 + o + 8)) * T_ + t;
            float2 x0 = *(const float2*)&x[i0];
            float2 x1 = *(const float2*)&x[i1];
            float2 v0; v0.x = d[mt][nt][0] + x0.x; v0.y = d[mt][nt][1] + x0.y;
            float2 v1; v1.x = d[mt][nt][2] + x1.x; v1.y = d[mt][nt][3] + x1.y;
            *(float2*)&out[i0] = v0;
            *(float2*)&out[i1] = v1;
        }
    }
}

// ---------------- launch ----------------
extern "C" void kernel_launch(void* const* d_in, const int* in_sizes, int n_in,
                              void* d_out, int out_size) {
    (void)in_sizes; (void)n_in; (void)out_size;
    const float* x  = (const float*)d_in[0];
    const float* a1 = (const float*)d_in[1];
    const float* b1 = (const float*)d_in[2];
    const float* v1 = (const float*)d_in[3];
    const float* g1 = (const float*)d_in[4];
    const float* a2 = (const float*)d_in[5];
    const float* b2 = (const float*)d_in[6];
    const float* v2 = (const float*)d_in[7];
    const float* g2 = (const float*)d_in[8];
    const float* v3 = (const float*)d_in[9];
    const float* g3 = (const float*)d_in[10];
    float* out = (float*)d_out;

    float *w2p = nullptr, *w3p = nullptr, *h2p = nullptr;
    __nv_bfloat16 *xhip = nullptr, *xlop = nullptr, *yhip = nullptr, *ylop = nullptr;
    cudaGetSymbolAddress((void**)&w2p, g_w2);
    cudaGetSymbolAddress((void**)&w3p, g_w3);
    cudaGetSymbolAddress((void**)&h2p, g_h2);
    cudaGetSymbolAddress((void**)&xhip, g_xhi);
    cudaGetSymbolAddress((void**)&xlop, g_xlo);
    cudaGetSymbolAddress((void**)&yhip, g_yhi);
    cudaGetSymbolAddress((void**)&ylop, g_ylo);

    cudaFuncSetAttribute(k_conv1_m, cudaFuncAttributeMaxDynamicSharedMemorySize, SM_SZ);
    cudaFuncSetAttribute(k_conv23_m, cudaFuncAttributeMaxDynamicSharedMemorySize, SM_SZ);

    k_filt<<<1, 32>>>();                                          // 1
    k_wnorm1<<<C_, 256>>>(v1, g1);                                // 2
    k_wnorm<<<C4_, 256>>>(v2, g2, w2p, C_);                       // 3
    k_wnorm<<<C_,  256>>>(v3, g3, w3p, C4_);                      // 4
    k_act_split<<<B_ * C_, 256>>>(x, a1, b1, xhip, xlop);         // 5
    k_conv1_m<<<dim3(32, 4, 4), 256, SM_SZ>>>();                  // 6 (profiled)
    k_gemmW<<<dim3(8, 8, 8), 256>>>();                            // 7
    k_redW<<<1024, 256>>>();                                      // 8
    k_act_split<<<B_ * C_, 256>>>(h2p, a2, b2, yhip, ylop);       // 9
    k_conv23_m<<<dim3(32, 4, 4), 256, SM_SZ>>>(x, out);           // 10
}